// round 4
// baseline (speedup 1.0000x reference)
#include <cuda_runtime.h>
#include <cstdint>
#include <math.h>

// ---------------- problem constants ----------------
#define BB   4
#define NX   4096
#define NY   8192
#define DD   256
#define TM   128                 // x rows per CTA
#define TN   128                 // y cols per tile
#define KC   32                  // k per chunk
#define NT   (NY / TN)           // 64 y tiles
#define NCH  (DD / KC)           // 8 chunks per tile
#define NCC  (NT * NCH)          // 512 chunk iterations
#define KK   10
#define NROW (BB * NX)
#define NVAL (NROW * KK)         // 163840
#define INV_TAU 20.0f
#define NTHR 512

// scratch: x normalized row-major, y normalized TRANSPOSED [b][k][j]
__device__ float g_xn[(size_t)BB * NX * DD];
__device__ float g_ynT[(size_t)BB * DD * NY];

// ---------------- helpers ----------------
__device__ __forceinline__ uint32_t cvta_s(const void* p) {
    return (uint32_t)__cvta_generic_to_shared(p);
}
__device__ __forceinline__ unsigned long long lds64(uint32_t a) {
    unsigned long long v;
    asm volatile("ld.shared.b64 %0, [%1];" : "=l"(v) : "r"(a));
    return v;
}
__device__ __forceinline__ float2 lds_f2(uint32_t a) {
    float2 v;
    asm volatile("ld.shared.v2.f32 {%0,%1}, [%2];" : "=f"(v.x), "=f"(v.y) : "r"(a));
    return v;
}
__device__ __forceinline__ void sts64(uint32_t a, unsigned long long v) {
    asm volatile("st.shared.b64 [%0], %1;" :: "r"(a), "l"(v));
}
__device__ __forceinline__ unsigned long long dup2(float v) {
    unsigned long long d;
    asm("mov.b64 %0, {%1,%1};" : "=l"(d) : "f"(v));
    return d;
}
__device__ __forceinline__ void ffma2(unsigned long long& d,
                                      unsigned long long a,
                                      unsigned long long b) {
    asm("fma.rn.f32x2 %0, %1, %2, %0;" : "+l"(d) : "l"(a), "l"(b));
}
__device__ __forceinline__ void cp16(uint32_t dst, const void* src) {
    asm volatile("cp.async.cg.shared.global [%0], [%1], 16;" :: "r"(dst), "l"(src));
}
__device__ __forceinline__ void cp_commit() { asm volatile("cp.async.commit_group;"); }
template <int N>
__device__ __forceinline__ void cp_wait() { asm volatile("cp.async.wait_group %0;" :: "n"(N)); }

// ---------------- kernel 1a: normalize X rows (row-major out) ----------------
__global__ void norm_x_kernel(const float* __restrict__ fx) {
    int wid  = (blockIdx.x * blockDim.x + threadIdx.x) >> 5;
    int lane = threadIdx.x & 31;
    if (wid >= BB * NX) return;
    const float4* s4 = (const float4*)(fx + (size_t)wid * DD);
    float4 a = s4[lane];
    float4 b = s4[lane + 32];
    float s = a.x*a.x + a.y*a.y + a.z*a.z + a.w*a.w
            + b.x*b.x + b.y*b.y + b.z*b.z + b.w*b.w;
#pragma unroll
    for (int off = 16; off > 0; off >>= 1) s += __shfl_xor_sync(0xffffffffu, s, off);
    float inv = 1.0f / fmaxf(sqrtf(s), 1e-12f);
    float4* d4 = (float4*)(g_xn + (size_t)wid * DD);
    a.x*=inv; a.y*=inv; a.z*=inv; a.w*=inv;
    b.x*=inv; b.y*=inv; b.z*=inv; b.w*=inv;
    d4[lane] = a;
    d4[lane + 32] = b;
}

// ---------------- kernel 1b: normalize Y rows, write TRANSPOSED ----------------
__global__ void norm_y_kernel(const float* __restrict__ fy) {
    __shared__ float buf[32 * 257];
    int blk = blockIdx.x;
    int b   = blk >> 8;
    int j0  = (blk & 255) * 32;
    int tid = threadIdx.x;
    int w   = tid >> 5;
    int lane = tid & 31;

#pragma unroll
    for (int rr = 0; rr < 4; rr++) {
        int row = w * 4 + rr;
        const float4* s4 = (const float4*)(fy + ((size_t)b * NY + j0 + row) * DD);
        float4 a = s4[lane];
        float4 bb = s4[lane + 32];
        float s = a.x*a.x + a.y*a.y + a.z*a.z + a.w*a.w
                + bb.x*bb.x + bb.y*bb.y + bb.z*bb.z + bb.w*bb.w;
#pragma unroll
        for (int off = 16; off > 0; off >>= 1) s += __shfl_xor_sync(0xffffffffu, s, off);
        float inv = 1.0f / fmaxf(sqrtf(s), 1e-12f);
        float* br = buf + row * 257;
        br[lane*4 + 0] = a.x * inv;  br[lane*4 + 1] = a.y * inv;
        br[lane*4 + 2] = a.z * inv;  br[lane*4 + 3] = a.w * inv;
        br[128 + lane*4 + 0] = bb.x * inv;  br[128 + lane*4 + 1] = bb.y * inv;
        br[128 + lane*4 + 2] = bb.z * inv;  br[128 + lane*4 + 3] = bb.w * inv;
    }
    __syncthreads();

#pragma unroll 8
    for (int rep = 0; rep < 32; rep++) {
        int e = rep * 256 + tid;
        int k = e >> 5;
        int j = e & 31;
        g_ynT[((size_t)b * DD + k) * NY + j0 + j] = buf[j * 257 + k];
    }
}

// ---------------- kernel 2: 128x128 tiles, 512 threads, 4x8 micro-tile ----------------
// smem layout (bytes):
//   XS  [0,      131072)  x tile: 128 rows x 64 16B-units, XOR-swizzled by (row>>3)&7
//   YS  [131072, 163840)  2 x (32k x 128j) k-major y chunks
//   SIM [163840, 197120)  64 x 130 floats (half-tile staging)
//   LV  [197120, 202240)  128 x 10 floats
//   LI  [202240, 207360)  128 x 10 ints
#define SM_XS   0
#define SM_YS   131072
#define SM_SIM  163840
#define SM_LV   197120
#define SM_LI   202240
#define SM_TOT  207360
#define SIMP    130

extern __shared__ unsigned char smem_raw[];

__global__ void __launch_bounds__(NTHR, 1)
sim_topk_kernel(float* __restrict__ out, int out_size) {
    const int b   = blockIdx.y;
    const int xt  = blockIdx.x;
    const int tid = threadIdx.x;
    const int ty  = tid >> 4;   // 0..31 -> x rows ty*4..ty*4+3
    const int tx  = tid & 15;   // y col pairs: tx+16m, m=0..3

    uint32_t s0  = cvta_s(smem_raw);
    float*   SIM = (float*)(smem_raw + SM_SIM);
    float*   LV  = (float*)(smem_raw + SM_LV);
    int*     LI  = (int*)(smem_raw + SM_LI);

    for (int i = tid; i < TM * KK; i += NTHR) { LV[i] = -1e38f; LI[i] = 0; }

    // ---- load X tile (128 x 256 floats), swizzle unit q' = q ^ ((row>>3)&7) ----
    {
        const float4* gx = (const float4*)(g_xn + ((size_t)b * NX + (size_t)xt * TM) * DD);
#pragma unroll
        for (int r = 0; r < 16; r++) {
            int idx = r * NTHR + tid;          // 8192 16B units
            int i = idx >> 6, q = idx & 63;
            int qp = q ^ ((i >> 3) & 7);
            cp16(s0 + SM_XS + (uint32_t)((i << 10) + (qp << 4)), gx + idx);
        }
    }
    // ---- load y chunk 0 ----
    {
        const float* gy = g_ynT + (size_t)b * DD * NY;
#pragma unroll
        for (int r = 0; r < 2; r++) {
            int e = r * NTHR + tid;            // 1024 units
            int k = e >> 5, q = e & 31;
            cp16(s0 + SM_YS + (uint32_t)((k << 9) + (q << 4)),
                 gy + (size_t)k * NY + q * 4);
        }
    }
    cp_commit();

    uint32_t xrb[4];
#pragma unroll
    for (int ii = 0; ii < 4; ii++)
        xrb[ii] = s0 + SM_XS + (uint32_t)(((ty << 2) + ii) << 10);
    uint32_t yb_pair[4];
#pragma unroll
    for (int m = 0; m < 4; m++)
        yb_pair[m] = (uint32_t)((tx + 16 * m) << 3);
    const int xsw = (ty >> 1) & 7;

    unsigned long long acc[4][4];

    for (int cc = 0; cc < NCC; cc++) {
        const int c = cc & 7;        // chunk within tile
        const int t = cc >> 3;       // y tile

        if (cc + 1 < NCC) {
            int cn = (cc + 1) & 7, tn = (cc + 1) >> 3;
            const float* gy = g_ynT + ((size_t)b * DD + cn * KC) * NY + (size_t)tn * TN;
            uint32_t dstb = s0 + SM_YS + (uint32_t)(((cc + 1) & 1) << 14);
#pragma unroll
            for (int r = 0; r < 2; r++) {
                int e = r * NTHR + tid;
                int k = e >> 5, q = e & 31;
                cp16(dstb + (uint32_t)((k << 9) + (q << 4)), gy + (size_t)k * NY + q * 4);
            }
            cp_commit();
            cp_wait<1>();
        } else {
            cp_wait<0>();
        }
        __syncthreads();

        if (c == 0) {
#pragma unroll
            for (int ii = 0; ii < 4; ii++)
#pragma unroll
                for (int m = 0; m < 4; m++) acc[ii][m] = 0ull;
        }

        const uint32_t ybase = s0 + SM_YS + (uint32_t)((cc & 1) << 14);

        // ---- FMA over 32 k (16 pairs); X unit includes chunk base c*8 ----
#pragma unroll 4
        for (int s = 0; s < 16; s++) {
            uint32_t xoff = (uint32_t)((((c << 3) + ((s >> 1) ^ xsw)) << 4) + ((s & 1) << 3));
            float2 xv[4];
#pragma unroll
            for (int ii = 0; ii < 4; ii++) xv[ii] = lds_f2(xrb[ii] + xoff);
#pragma unroll
            for (int u = 0; u < 2; u++) {
                uint32_t yrow = ybase + (uint32_t)(((2 * s + u) << 9));
                unsigned long long yv[4];
#pragma unroll
                for (int m = 0; m < 4; m++) yv[m] = lds64(yrow + yb_pair[m]);
#pragma unroll
                for (int ii = 0; ii < 4; ii++) {
                    unsigned long long xd = dup2(u ? xv[ii].y : xv[ii].x);
#pragma unroll
                    for (int m = 0; m < 4; m++) ffma2(acc[ii][m], xd, yv[m]);
                }
            }
        }
        __syncthreads();

        // ---- tile finished: stage sim in 2 halves, update top-k ----
        if (c == 7) {
            const int col0 = t * TN;
#pragma unroll
            for (int h = 0; h < 2; h++) {
                if ((ty >> 4) == h) {
                    int rbase = (ty & 15) * 4;
#pragma unroll
                    for (int ii = 0; ii < 4; ii++) {
                        uint32_t a = s0 + SM_SIM + (uint32_t)((rbase + ii) * SIMP * 4);
#pragma unroll
                        for (int m = 0; m < 4; m++)
                            sts64(a + (uint32_t)((tx + 16 * m) << 3), acc[ii][m]);
                    }
                }
                __syncthreads();
                if (tid < 64) {
                    int row = h * 64 + tid;
                    float* lv = LV + row * KK;
                    int*   li = LI + row * KK;
                    const float* srow = SIM + tid * SIMP;
                    float lv9 = lv[KK - 1];
#pragma unroll 4
                    for (int cL = 0; cL < TN; cL++) {
                        float vv = srow[cL];
                        if (vv > lv9) {
                            int p = KK - 1;
                            while (p > 0 && lv[p - 1] < vv) {
                                lv[p] = lv[p - 1]; li[p] = li[p - 1]; --p;
                            }
                            lv[p] = vv; li[p] = col0 + cL;
                            lv9 = lv[KK - 1];
                        }
                    }
                }
                __syncthreads();
            }
        }
    }

    // ---- finalize: softmax + sort-by-col + write ----
    if (tid < TM) {
        float v[KK]; int ix[KK];
#pragma unroll
        for (int k = 0; k < KK; k++) { v[k] = LV[tid * KK + k]; ix[k] = LI[tid * KK + k]; }
        float m = v[0];
        float e[KK]; float ssum = 0.0f;
#pragma unroll
        for (int k = 0; k < KK; k++) { e[k] = expf((v[k] - m) * INV_TAU); ssum += e[k]; }
        float inv = 1.0f / ssum;
#pragma unroll
        for (int a = 1; a < KK; a++) {
            int ki = ix[a]; float ke = e[a]; int p = a;
            while (p > 0 && ix[p - 1] > ki) { ix[p] = ix[p - 1]; e[p] = e[p - 1]; --p; }
            ix[p] = ki; e[p] = ke;
        }
        int gRow = xt * TM + tid;
        size_t basev = ((size_t)b * NX + gRow) * KK;
        bool write_idx = (out_size >= 4 * NVAL);
#pragma unroll
        for (int k = 0; k < KK; k++) {
            out[basev + k] = e[k] * inv;
            if (write_idx) {
                out[(size_t)NVAL     + basev + k] = (float)b;
                out[(size_t)2 * NVAL + basev + k] = (float)gRow;
                out[(size_t)3 * NVAL + basev + k] = (float)ix[k];
            }
        }
    }
}

// ---------------- launch ----------------
extern "C" void kernel_launch(void* const* d_in, const int* in_sizes, int n_in,
                              void* d_out, int out_size) {
    const float* fx = (const float*)d_in[0];
    const float* fy = (const float*)d_in[1];
    float* out = (float*)d_out;

    norm_x_kernel<<<(BB * NX) / 8, 256>>>(fx);
    norm_y_kernel<<<(BB * NY) / 32, 256>>>(fy);

    cudaFuncSetAttribute(sim_topk_kernel,
                         cudaFuncAttributeMaxDynamicSharedMemorySize, SM_TOT);
    dim3 g2(NX / TM, BB);                            // 128 CTAs
    sim_topk_kernel<<<g2, NTHR, SM_TOT>>>(out, out_size);
}

// round 5
// speedup vs baseline: 1.0871x; 1.0871x over previous
#include <cuda_runtime.h>
#include <cstdint>
#include <math.h>

// ---------------- problem constants ----------------
#define BB   4
#define NX   4096
#define NY   8192
#define DD   256
#define TM   128                 // x rows per CTA
#define TN   128                 // y cols per tile
#define KC   32                  // k per chunk
#define NT   (NY / TN)           // 64 y tiles
#define NCH  (DD / KC)           // 8 chunks per tile
#define NCC  (NT * NCH)          // 512 chunk iterations
#define KK   10
#define NROW (BB * NX)
#define NVAL (NROW * KK)         // 163840
#define INV_TAU 20.0f
#define NTHR 512

// scratch: x normalized row-major, y normalized TRANSPOSED [b][k][j]
__device__ float g_xn[(size_t)BB * NX * DD];
__device__ float g_ynT[(size_t)BB * DD * NY];

// ---------------- helpers ----------------
__device__ __forceinline__ uint32_t cvta_s(const void* p) {
    return (uint32_t)__cvta_generic_to_shared(p);
}
__device__ __forceinline__ unsigned long long lds64(uint32_t a) {
    unsigned long long v;
    asm volatile("ld.shared.b64 %0, [%1];" : "=l"(v) : "r"(a));
    return v;
}
__device__ __forceinline__ float4 lds128(uint32_t a) {
    float4 v;
    asm volatile("ld.shared.v4.f32 {%0,%1,%2,%3}, [%4];"
                 : "=f"(v.x), "=f"(v.y), "=f"(v.z), "=f"(v.w) : "r"(a));
    return v;
}
__device__ __forceinline__ void sts64(uint32_t a, unsigned long long v) {
    asm volatile("st.shared.b64 [%0], %1;" :: "r"(a), "l"(v));
}
__device__ __forceinline__ unsigned long long dup2(float v) {
    unsigned long long d;
    asm("mov.b64 %0, {%1,%1};" : "=l"(d) : "f"(v));
    return d;
}
__device__ __forceinline__ void ffma2(unsigned long long& d,
                                      unsigned long long a,
                                      unsigned long long b) {
    asm("fma.rn.f32x2 %0, %1, %2, %0;" : "+l"(d) : "l"(a), "l"(b));
}
__device__ __forceinline__ void cp16(uint32_t dst, const void* src) {
    asm volatile("cp.async.cg.shared.global [%0], [%1], 16;" :: "r"(dst), "l"(src));
}
__device__ __forceinline__ void cp_commit() { asm volatile("cp.async.commit_group;"); }
template <int N>
__device__ __forceinline__ void cp_wait() { asm volatile("cp.async.wait_group %0;" :: "n"(N)); }

// ---------------- kernel 1a: normalize X rows ----------------
__global__ void norm_x_kernel(const float* __restrict__ fx) {
    int wid  = (blockIdx.x * blockDim.x + threadIdx.x) >> 5;
    int lane = threadIdx.x & 31;
    if (wid >= BB * NX) return;
    const float4* s4 = (const float4*)(fx + (size_t)wid * DD);
    float4 a = s4[lane];
    float4 b = s4[lane + 32];
    float s = a.x*a.x + a.y*a.y + a.z*a.z + a.w*a.w
            + b.x*b.x + b.y*b.y + b.z*b.z + b.w*b.w;
#pragma unroll
    for (int off = 16; off > 0; off >>= 1) s += __shfl_xor_sync(0xffffffffu, s, off);
    float inv = 1.0f / fmaxf(sqrtf(s), 1e-12f);
    float4* d4 = (float4*)(g_xn + (size_t)wid * DD);
    a.x*=inv; a.y*=inv; a.z*=inv; a.w*=inv;
    b.x*=inv; b.y*=inv; b.z*=inv; b.w*=inv;
    d4[lane] = a;
    d4[lane + 32] = b;
}

// ---------------- kernel 1b: normalize Y rows, write TRANSPOSED ----------------
__global__ void norm_y_kernel(const float* __restrict__ fy) {
    __shared__ float buf[32 * 257];
    int blk = blockIdx.x;
    int b   = blk >> 8;
    int j0  = (blk & 255) * 32;
    int tid = threadIdx.x;
    int w   = tid >> 5;
    int lane = tid & 31;

#pragma unroll
    for (int rr = 0; rr < 4; rr++) {
        int row = w * 4 + rr;
        const float4* s4 = (const float4*)(fy + ((size_t)b * NY + j0 + row) * DD);
        float4 a = s4[lane];
        float4 bb = s4[lane + 32];
        float s = a.x*a.x + a.y*a.y + a.z*a.z + a.w*a.w
                + bb.x*bb.x + bb.y*bb.y + bb.z*bb.z + bb.w*bb.w;
#pragma unroll
        for (int off = 16; off > 0; off >>= 1) s += __shfl_xor_sync(0xffffffffu, s, off);
        float inv = 1.0f / fmaxf(sqrtf(s), 1e-12f);
        float* br = buf + row * 257;
        br[lane*4 + 0] = a.x * inv;  br[lane*4 + 1] = a.y * inv;
        br[lane*4 + 2] = a.z * inv;  br[lane*4 + 3] = a.w * inv;
        br[128 + lane*4 + 0] = bb.x * inv;  br[128 + lane*4 + 1] = bb.y * inv;
        br[128 + lane*4 + 2] = bb.z * inv;  br[128 + lane*4 + 3] = bb.w * inv;
    }
    __syncthreads();

#pragma unroll 8
    for (int rep = 0; rep < 32; rep++) {
        int e = rep * 256 + tid;
        int k = e >> 5;
        int j = e & 31;
        g_ynT[((size_t)b * DD + k) * NY + j0 + j] = buf[j * 257 + k];
    }
}

// ---------------- kernel 2: 128x128 tiles, 512 threads, 4x8 micro-tile ----------------
// smem layout (bytes):
//   XS  [0,      131072)  x tile: 128 rows x 64 16B-units, XOR-swizzled by (row>>2)&7
//   YS  [131072, 163840)  2 x (32k x 128j) k-major y chunks
//   SIM [163840, 197120)  64 x 130 floats (half-tile staging)
//   LV  [197120, 202240)  128 x 10 floats
//   LI  [202240, 207360)  128 x 10 ints
#define SM_XS   0
#define SM_YS   131072
#define SM_SIM  163840
#define SM_LV   197120
#define SM_LI   202240
#define SM_TOT  207360
#define SIMP    130

extern __shared__ unsigned char smem_raw[];

__global__ void __launch_bounds__(NTHR, 1)
sim_topk_kernel(float* __restrict__ out, int out_size) {
    const int b   = blockIdx.y;
    const int xt  = blockIdx.x;
    const int tid = threadIdx.x;
    const int ty  = tid >> 4;   // 0..31 -> x rows ty*4..ty*4+3
    const int tx  = tid & 15;   // y col pairs: tx+16m, m=0..3

    uint32_t s0  = cvta_s(smem_raw);
    float*   SIM = (float*)(smem_raw + SM_SIM);
    float*   LV  = (float*)(smem_raw + SM_LV);
    int*     LI  = (int*)(smem_raw + SM_LI);

    for (int i = tid; i < TM * KK; i += NTHR) { LV[i] = -1e38f; LI[i] = 0; }

    // ---- load X tile, swizzle unit q' = q ^ ((row>>2)&7) ----
    {
        const float4* gx = (const float4*)(g_xn + ((size_t)b * NX + (size_t)xt * TM) * DD);
#pragma unroll
        for (int r = 0; r < 16; r++) {
            int idx = r * NTHR + tid;          // 8192 16B units
            int i = idx >> 6, q = idx & 63;
            int qp = q ^ ((i >> 2) & 7);
            cp16(s0 + SM_XS + (uint32_t)((i << 10) + (qp << 4)), gx + idx);
        }
    }
    // ---- load y chunk 0 ----
    {
        const float* gy = g_ynT + (size_t)b * DD * NY;
#pragma unroll
        for (int r = 0; r < 2; r++) {
            int e = r * NTHR + tid;            // 1024 units
            int k = e >> 5, q = e & 31;
            cp16(s0 + SM_YS + (uint32_t)((k << 9) + (q << 4)),
                 gy + (size_t)k * NY + q * 4);
        }
    }
    cp_commit();

    uint32_t xrb[4];
#pragma unroll
    for (int ii = 0; ii < 4; ii++)
        xrb[ii] = s0 + SM_XS + (uint32_t)(((ty << 2) + ii) << 10);
    uint32_t yb_pair[4];
#pragma unroll
    for (int m = 0; m < 4; m++)
        yb_pair[m] = (uint32_t)((tx + 16 * m) << 3);
    const int xsw = ty & 7;    // differs between the two ty of a warp -> no bank conflict

    unsigned long long acc[4][4];

    for (int cc = 0; cc < NCC; cc++) {
        const int c = cc & 7;        // chunk within tile
        const int t = cc >> 3;       // y tile

        if (cc + 1 < NCC) {
            int cn = (cc + 1) & 7, tn = (cc + 1) >> 3;
            const float* gy = g_ynT + ((size_t)b * DD + cn * KC) * NY + (size_t)tn * TN;
            uint32_t dstb = s0 + SM_YS + (uint32_t)(((cc + 1) & 1) << 14);
#pragma unroll
            for (int r = 0; r < 2; r++) {
                int e = r * NTHR + tid;
                int k = e >> 5, q = e & 31;
                cp16(dstb + (uint32_t)((k << 9) + (q << 4)), gy + (size_t)k * NY + q * 4);
            }
            cp_commit();
            cp_wait<1>();
        } else {
            cp_wait<0>();
        }
        __syncthreads();

        if (c == 0) {
#pragma unroll
            for (int ii = 0; ii < 4; ii++)
#pragma unroll
                for (int m = 0; m < 4; m++) acc[ii][m] = 0ull;
        }

        const uint32_t ybase = s0 + SM_YS + (uint32_t)((cc & 1) << 14);

        // ---- FMA over 32 k: 8 groups of 4 k; x loaded as 16B (4 k) per row ----
#pragma unroll
        for (int g = 0; g < 8; g++) {
            uint32_t xoff = (uint32_t)(((c << 3) + (g ^ xsw)) << 4);
            float4 xv[4];
#pragma unroll
            for (int ii = 0; ii < 4; ii++) xv[ii] = lds128(xrb[ii] + xoff);
#pragma unroll
            for (int u = 0; u < 4; u++) {
                uint32_t yrow = ybase + (uint32_t)(((g * 4 + u) << 9));
                unsigned long long yv[4];
#pragma unroll
                for (int m = 0; m < 4; m++) yv[m] = lds64(yrow + yb_pair[m]);
#pragma unroll
                for (int ii = 0; ii < 4; ii++) {
                    float xs = (u == 0) ? xv[ii].x : (u == 1) ? xv[ii].y
                             : (u == 2) ? xv[ii].z : xv[ii].w;
                    unsigned long long xd = dup2(xs);
#pragma unroll
                    for (int m = 0; m < 4; m++) ffma2(acc[ii][m], xd, yv[m]);
                }
            }
        }
        __syncthreads();

        // ---- tile finished: stage sim in 2 halves, update top-k ----
        if (c == 7) {
            const int col0 = t * TN;
#pragma unroll
            for (int h = 0; h < 2; h++) {
                if ((ty >> 4) == h) {
                    int rbase = (ty & 15) * 4;
#pragma unroll
                    for (int ii = 0; ii < 4; ii++) {
                        uint32_t a = s0 + SM_SIM + (uint32_t)((rbase + ii) * SIMP * 4);
#pragma unroll
                        for (int m = 0; m < 4; m++)
                            sts64(a + (uint32_t)((tx + 16 * m) << 3), acc[ii][m]);
                    }
                }
                __syncthreads();
                if (tid < 64) {
                    int row = h * 64 + tid;
                    float* lv = LV + row * KK;
                    int*   li = LI + row * KK;
                    const float* srow = SIM + tid * SIMP;
                    float lv9 = lv[KK - 1];
#pragma unroll 4
                    for (int cL = 0; cL < TN; cL++) {
                        float vv = srow[cL];
                        if (vv > lv9) {
                            int p = KK - 1;
                            while (p > 0 && lv[p - 1] < vv) {
                                lv[p] = lv[p - 1]; li[p] = li[p - 1]; --p;
                            }
                            lv[p] = vv; li[p] = col0 + cL;
                            lv9 = lv[KK - 1];
                        }
                    }
                }
                __syncthreads();
            }
        }
    }

    // ---- finalize: softmax + sort-by-col + write ----
    if (tid < TM) {
        float v[KK]; int ix[KK];
#pragma unroll
        for (int k = 0; k < KK; k++) { v[k] = LV[tid * KK + k]; ix[k] = LI[tid * KK + k]; }
        float m = v[0];
        float e[KK]; float ssum = 0.0f;
#pragma unroll
        for (int k = 0; k < KK; k++) { e[k] = expf((v[k] - m) * INV_TAU); ssum += e[k]; }
        float inv = 1.0f / ssum;
#pragma unroll
        for (int a = 1; a < KK; a++) {
            int ki = ix[a]; float ke = e[a]; int p = a;
            while (p > 0 && ix[p - 1] > ki) { ix[p] = ix[p - 1]; e[p] = e[p - 1]; --p; }
            ix[p] = ki; e[p] = ke;
        }
        int gRow = xt * TM + tid;
        size_t basev = ((size_t)b * NX + gRow) * KK;
        bool write_idx = (out_size >= 4 * NVAL);
#pragma unroll
        for (int k = 0; k < KK; k++) {
            out[basev + k] = e[k] * inv;
            if (write_idx) {
                out[(size_t)NVAL     + basev + k] = (float)b;
                out[(size_t)2 * NVAL + basev + k] = (float)gRow;
                out[(size_t)3 * NVAL + basev + k] = (float)ix[k];
            }
        }
    }
}

// ---------------- launch ----------------
extern "C" void kernel_launch(void* const* d_in, const int* in_sizes, int n_in,
                              void* d_out, int out_size) {
    const float* fx = (const float*)d_in[0];
    const float* fy = (const float*)d_in[1];
    float* out = (float*)d_out;

    norm_x_kernel<<<(BB * NX) / 8, 256>>>(fx);
    norm_y_kernel<<<(BB * NY) / 32, 256>>>(fy);

    cudaFuncSetAttribute(sim_topk_kernel,
                         cudaFuncAttributeMaxDynamicSharedMemorySize, SM_TOT);
    dim3 g2(NX / TM, BB);                            // 128 CTAs
    sim_topk_kernel<<<g2, NTHR, SM_TOT>>>(out, out_size);
}

// round 7
// speedup vs baseline: 1.1484x; 1.0563x over previous
#include <cuda_runtime.h>
#include <cstdint>
#include <math.h>

// ---------------- problem constants ----------------
#define BB   4
#define NX   4096
#define NY   8192
#define DD   256
#define TMR  128                 // x rows per CTA
#define TNC  128                 // y cols per tile
#define KCH  32                  // k per chunk
#define NTIL (NY / TNC)          // 64 y tiles
#define NCHK (DD / KCH)          // 8 chunks per tile
#define CHTOT (NTIL * NCHK)      // 512 chunk iterations
#define KK   10
#define NVAL (BB * NX * KK)      // 163840
#define INV_TAU 20.0f

// tf32-split scratch (row-major K-major, no transpose needed)
__device__ float g_xhi[(size_t)BB * NX * DD];
__device__ float g_xlo[(size_t)BB * NX * DD];
__device__ float g_yhi[(size_t)BB * NY * DD];
__device__ float g_ylo[(size_t)BB * NY * DD];

// ---------------- smem layout (bytes) ----------------
// row stride 36 floats = 144 B (bank-conflict-free fragment loads)
#define XROWB   144
#define HALF_SZ (128 * XROWB)        // 18432 (one of hi/lo)
#define STG_SZ  (2 * HALF_SZ)        // 36864 per stage per operand
#define SM_X0   0                    // X stages: [0, 73728)
#define SM_Y0   73728                // Y stages: [73728, 147456)
#define SM_SIM  147456               // 64 x 133 floats = 34048
#define SM_LV   181504               // 128*10*4 = 5120
#define SM_LI   186624               // 5120
#define SM_TOT  191744
#define SIMP    133

// ---------------- helpers ----------------
static __device__ __forceinline__ uint32_t cvta_s(const void* p) {
    return (uint32_t)__cvta_generic_to_shared(p);
}
static __device__ __forceinline__ uint32_t lds32(uint32_t a) {
    uint32_t v;
    asm volatile("ld.shared.b32 %0, [%1];" : "=r"(v) : "r"(a));
    return v;
}
static __device__ __forceinline__ void cp16(uint32_t d, const void* s) {
    asm volatile("cp.async.cg.shared.global [%0], [%1], 16;" :: "r"(d), "l"(s));
}
static __device__ __forceinline__ void cp_commit() { asm volatile("cp.async.commit_group;"); }
template <int N> static __device__ __forceinline__ void cp_wait() {
    asm volatile("cp.async.wait_group %0;" :: "n"(N));
}
static __device__ __forceinline__ void mma8(float* d, const uint32_t* a,
                                            uint32_t b0, uint32_t b1) {
    asm volatile(
        "mma.sync.aligned.m16n8k8.row.col.f32.tf32.tf32.f32 "
        "{%0,%1,%2,%3}, {%4,%5,%6,%7}, {%8,%9}, {%0,%1,%2,%3};"
        : "+f"(d[0]), "+f"(d[1]), "+f"(d[2]), "+f"(d[3])
        : "r"(a[0]), "r"(a[1]), "r"(a[2]), "r"(a[3]), "r"(b0), "r"(b1));
}
static __device__ __forceinline__ void split_tf32(float v, float& hi, float& lo) {
    uint32_t u;
    asm("cvt.rna.tf32.f32 %0, %1;" : "=r"(u) : "f"(v));
    hi = __uint_as_float(u);
    lo = v - hi;
}

// ---------------- kernel 1: normalize + tf32-split ----------------
__global__ void norm_split_kernel(const float* __restrict__ fx, const float* __restrict__ fy) {
    int wid  = (blockIdx.x * blockDim.x + threadIdx.x) >> 5;
    int lane = threadIdx.x & 31;
    const int totx = BB * NX;
    if (wid >= totx + BB * NY) return;
    const float* src; float *dhi, *dlo;
    if (wid < totx) {
        src = fx + (size_t)wid * DD;
        dhi = g_xhi + (size_t)wid * DD;  dlo = g_xlo + (size_t)wid * DD;
    } else {
        int r = wid - totx;
        src = fy + (size_t)r * DD;
        dhi = g_yhi + (size_t)r * DD;    dlo = g_ylo + (size_t)r * DD;
    }
    float4 a = ((const float4*)src)[lane];
    float4 b = ((const float4*)src)[lane + 32];
    float s = a.x*a.x + a.y*a.y + a.z*a.z + a.w*a.w
            + b.x*b.x + b.y*b.y + b.z*b.z + b.w*b.w;
#pragma unroll
    for (int off = 16; off > 0; off >>= 1) s += __shfl_xor_sync(0xffffffffu, s, off);
    float inv = 1.0f / fmaxf(sqrtf(s), 1e-12f);
    float4 hi0, lo0, hi1, lo1;
    split_tf32(a.x * inv, hi0.x, lo0.x);  split_tf32(a.y * inv, hi0.y, lo0.y);
    split_tf32(a.z * inv, hi0.z, lo0.z);  split_tf32(a.w * inv, hi0.w, lo0.w);
    split_tf32(b.x * inv, hi1.x, lo1.x);  split_tf32(b.y * inv, hi1.y, lo1.y);
    split_tf32(b.z * inv, hi1.z, lo1.z);  split_tf32(b.w * inv, hi1.w, lo1.w);
    ((float4*)dhi)[lane]      = hi0;  ((float4*)dhi)[lane + 32] = hi1;
    ((float4*)dlo)[lane]      = lo0;  ((float4*)dlo)[lane + 32] = lo1;
}

// ---------------- kernel 2: mma.sync 3xTF32 GEMM + fused top-k ----------------
extern __shared__ unsigned char smem_raw[];

__global__ void __launch_bounds__(256, 1)
sim_mma_kernel(float* __restrict__ out, int out_size) {
    const int b    = blockIdx.y;
    const int xt   = blockIdx.x;
    const int tid  = threadIdx.x;
    const int wid  = tid >> 5, lane = tid & 31;
    const int warpM = wid & 1;           // 2 warps along M (64 each)
    const int warpN = wid >> 1;          // 4 warps along N (32 each)
    const int gid  = lane >> 2;          // 0..7
    const int tig  = lane & 3;           // 0..3

    uint32_t s0 = cvta_s(smem_raw);
    float* SIM = (float*)(smem_raw + SM_SIM);
    float* LV  = (float*)(smem_raw + SM_LV);
    int*   LI  = (int*)(smem_raw + SM_LI);

    for (int i = tid; i < TMR * KK; i += 256) { LV[i] = -1e38f; LI[i] = 0; }
    __syncthreads();

    const float* xbh = g_xhi + ((size_t)b * NX + (size_t)xt * TMR) * DD;
    const float* xbl = g_xlo + ((size_t)b * NX + (size_t)xt * TMR) * DD;
    const float* ybh = g_yhi + (size_t)b * NY * DD;
    const float* ybl = g_ylo + (size_t)b * NY * DD;

    // per-thread cp.async slots: 4 rows-of-8 units each for X(hi,lo), Y(hi,lo)
    int frow[4], fq[4]; uint32_t foff[4];
#pragma unroll
    for (int i = 0; i < 4; i++) {
        int u = i * 256 + tid;           // 1024 16B units per half
        frow[i] = u >> 3; fq[i] = u & 7;
        foff[i] = (uint32_t)(frow[i] * XROWB + fq[i] * 16);
    }

    // fragment base byte offsets (within a 128x36f half)
    uint32_t aoff[4], boff[4];
#pragma unroll
    for (int m = 0; m < 4; m++)
        aoff[m] = (uint32_t)((warpM * 64 + m * 16 + gid) * XROWB + tig * 4);
#pragma unroll
    for (int n = 0; n < 4; n++)
        boff[n] = (uint32_t)((warpN * 32 + n * 8 + gid) * XROWB + tig * 4);

    float acc[4][4][4];

    // prologue: fill chunk 0 -> stage 0
    {
        const float* xh = xbh; const float* xl = xbl;
        const float* yh = ybh; const float* yl = ybl;
#pragma unroll
        for (int i = 0; i < 4; i++) {
            int so = frow[i] * DD + fq[i] * 4;
            cp16(s0 + SM_X0 + foff[i],           xh + so);
            cp16(s0 + SM_X0 + HALF_SZ + foff[i], xl + so);
            cp16(s0 + SM_Y0 + foff[i],           yh + so);
            cp16(s0 + SM_Y0 + HALF_SZ + foff[i], yl + so);
        }
        cp_commit();
    }

    for (int cc = 0; cc < CHTOT; cc++) {
        const int buf = cc & 1;
        const int c = cc & 7, t = cc >> 3;

        if (cc + 1 < CHTOT) {
            int nb = (cc + 1) & 1;
            int tn = (cc + 1) >> 3, cn = (cc + 1) & 7;
            int koff = cn * KCH;
            const float* xh = xbh + koff;
            const float* xl = xbl + koff;
            const float* yh = ybh + (size_t)tn * TNC * DD + koff;
            const float* yl = ybl + (size_t)tn * TNC * DD + koff;
            uint32_t xs = s0 + SM_X0 + (uint32_t)(nb * STG_SZ);
            uint32_t ys = s0 + SM_Y0 + (uint32_t)(nb * STG_SZ);
#pragma unroll
            for (int i = 0; i < 4; i++) {
                int so = frow[i] * DD + fq[i] * 4;
                cp16(xs + foff[i],           xh + so);
                cp16(xs + HALF_SZ + foff[i], xl + so);
                cp16(ys + foff[i],           yh + so);
                cp16(ys + HALF_SZ + foff[i], yl + so);
            }
            cp_commit();
            cp_wait<1>();
        } else {
            cp_wait<0>();
        }
        __syncthreads();

        if (c == 0) {
#pragma unroll
            for (int m = 0; m < 4; m++)
#pragma unroll
                for (int n = 0; n < 4; n++)
#pragma unroll
                    for (int j = 0; j < 4; j++) acc[m][n][j] = 0.0f;
        }

        const uint32_t xs = s0 + SM_X0 + (uint32_t)(buf * STG_SZ);
        const uint32_t ys = s0 + SM_Y0 + (uint32_t)(buf * STG_SZ);

        // 3 passes: Ah*Bh, Ah*Bl, Al*Bh
#pragma unroll
        for (int pass = 0; pass < 3; pass++) {
            const uint32_t A = xs + ((pass == 2) ? HALF_SZ : 0u);
            const uint32_t Bb = ys + ((pass == 1) ? HALF_SZ : 0u);
#pragma unroll
            for (int ks = 0; ks < 4; ks++) {
                const uint32_t kb = (uint32_t)(ks * 32);   // 8 floats
                uint32_t afr[4][4];
#pragma unroll
                for (int m = 0; m < 4; m++) {
                    afr[m][0] = lds32(A + aoff[m] + kb);
                    afr[m][1] = lds32(A + aoff[m] + kb + 8 * XROWB);
                    afr[m][2] = lds32(A + aoff[m] + kb + 16);
                    afr[m][3] = lds32(A + aoff[m] + kb + 8 * XROWB + 16);
                }
                uint32_t b0[4], b1[4];
#pragma unroll
                for (int n = 0; n < 4; n++) {
                    b0[n] = lds32(Bb + boff[n] + kb);
                    b1[n] = lds32(Bb + boff[n] + kb + 16);
                }
#pragma unroll
                for (int m = 0; m < 4; m++)
#pragma unroll
                    for (int n = 0; n < 4; n++)
                        mma8(acc[m][n], afr[m], b0[n], b1[n]);
            }
        }
        __syncthreads();

        // tile complete: stage SIM halves + top-k scan
        if (c == 7) {
            const int col0 = t * TNC;
#pragma unroll
            for (int h = 0; h < 2; h++) {
                if (warpM == h) {
#pragma unroll
                    for (int m = 0; m < 4; m++) {
                        int r0 = m * 16 + gid;
#pragma unroll
                        for (int n = 0; n < 4; n++) {
                            int col = warpN * 32 + n * 8 + 2 * tig;
                            SIM[r0 * SIMP + col]           = acc[m][n][0];
                            SIM[r0 * SIMP + col + 1]       = acc[m][n][1];
                            SIM[(r0 + 8) * SIMP + col]     = acc[m][n][2];
                            SIM[(r0 + 8) * SIMP + col + 1] = acc[m][n][3];
                        }
                    }
                }
                __syncthreads();
                if (tid < 64) {
                    int row = h * 64 + tid;
                    float* lv = LV + row * KK;
                    int*   li = LI + row * KK;
                    const float* srow = SIM + tid * SIMP;
                    float lv9 = lv[KK - 1];
#pragma unroll 4
                    for (int cL = 0; cL < TNC; cL++) {
                        float vv = srow[cL];
                        if (vv > lv9) {
                            int p = KK - 1;
                            while (p > 0 && lv[p - 1] < vv) {
                                lv[p] = lv[p - 1]; li[p] = li[p - 1]; --p;
                            }
                            lv[p] = vv; li[p] = col0 + cL;
                            lv9 = lv[KK - 1];
                        }
                    }
                }
                __syncthreads();
            }
        }
    }

    // ---- finalize: softmax + sort-by-col + write ----
    if (tid < TMR) {
        float v[KK]; int ix[KK];
#pragma unroll
        for (int k = 0; k < KK; k++) { v[k] = LV[tid * KK + k]; ix[k] = LI[tid * KK + k]; }
        float m = v[0];
        float e[KK]; float ssum = 0.0f;
#pragma unroll
        for (int k = 0; k < KK; k++) { e[k] = expf((v[k] - m) * INV_TAU); ssum += e[k]; }
        float inv = 1.0f / ssum;
#pragma unroll
        for (int a = 1; a < KK; a++) {
            int ki = ix[a]; float ke = e[a]; int p = a;
            while (p > 0 && ix[p - 1] > ki) { ix[p] = ix[p - 1]; e[p] = e[p - 1]; --p; }
            ix[p] = ki; e[p] = ke;
        }
        int gRow = xt * TMR + tid;
        size_t basev = ((size_t)b * NX + gRow) * KK;
        bool write_idx = (out_size >= 4 * NVAL);
#pragma unroll
        for (int k = 0; k < KK; k++) {
            out[basev + k] = e[k] * inv;
            if (write_idx) {
                out[(size_t)NVAL     + basev + k] = (float)b;
                out[(size_t)2 * NVAL + basev + k] = (float)gRow;
                out[(size_t)3 * NVAL + basev + k] = (float)ix[k];
            }
        }
    }
}

// ---------------- launch ----------------
extern "C" void kernel_launch(void* const* d_in, const int* in_sizes, int n_in,
                              void* d_out, int out_size) {
    const float* fx = (const float*)d_in[0];
    const float* fy = (const float*)d_in[1];
    float* out = (float*)d_out;

    int nrows = BB * NX + BB * NY;             // warp per row
    norm_split_kernel<<<(nrows + 7) / 8, 256>>>(fx, fy);

    cudaFuncSetAttribute(sim_mma_kernel,
                         cudaFuncAttributeMaxDynamicSharedMemorySize, SM_TOT);
    dim3 g2(NX / TMR, BB);                     // 32 x 4 = 128 CTAs
    sim_mma_kernel<<<g2, 256, SM_TOT>>>(out, out_size);
}